// round 8
// baseline (speedup 1.0000x reference)
#include <cuda_runtime.h>

// Problem constants
#define B_  4
#define H_  32
#define S_  2048
#define D_  128
#define BH_ (B_ * H_)          // 128
#define DM_ (H_ * D_)          // 4096
#define M_  (B_ * S_)          // 8192

// Scratch (device globals: no allocation allowed in kernel_launch)
__device__ float g_mem[BH_ * D_ * D_];        // [bh][k][v]  8 MB
__device__ float g_nrm[BH_ * D_];             // [bh][k]
__device__ float g_attn[M_ * DM_];            // [b*S+s][h*D+d]  128 MB

// ---------------------------------------------------------------------------
// helpers: packed f32x2 FMA (FFMA2) — 2x fp32 throughput on sm_103a
// ---------------------------------------------------------------------------
__device__ __forceinline__ float phi1(float x) {
    // elu(x)+1 :  x>0 -> x+1 ; else exp(x)
    return x > 0.f ? x + 1.f : __expf(x);
}

__device__ __forceinline__ unsigned long long fdup(float x) {
    unsigned long long r;
    asm("mov.b64 %0, {%1, %2};" : "=l"(r) : "f"(x), "f"(x));
    return r;
}

__device__ __forceinline__ void ffma2(unsigned long long& acc,
                                      unsigned long long a,
                                      unsigned long long b) {
    asm("fma.rn.f32x2 %0, %1, %2, %0;" : "+l"(acc) : "l"(a), "l"(b));
}

__device__ __forceinline__ float2 f2unpack(unsigned long long v) {
    float2 r;
    asm("mov.b64 {%0, %1}, %2;" : "=f"(r.x), "=f"(r.y) : "l"(v));
    return r;
}

// ---------------------------------------------------------------------------
// Kernel 1: memory[bh] = phiK^T @ V  (128x128, K-dim = S) + normalization sums
// one block per (b,h); 256 threads; thread tile 8x8
// ---------------------------------------------------------------------------
__global__ __launch_bounds__(256) void k_memory(const float* __restrict__ Kin,
                                                const float* __restrict__ Vin)
{
    __shared__ float sK[16][128];
    __shared__ float sV[16][128];

    const int bh  = blockIdx.x;
    const float* Kp = Kin + (size_t)bh * S_ * D_;
    const float* Vp = Vin + (size_t)bh * S_ * D_;
    const int tid = threadIdx.x;
    const int tx  = tid & 15, ty = tid >> 4;
    const int k0  = ty * 8,  v0 = tx * 8;

    unsigned long long acc[8][4];
#pragma unroll
    for (int i = 0; i < 8; i++)
#pragma unroll
        for (int j = 0; j < 4; j++) acc[i][j] = 0ULL;
    float nacc = 0.f;

    for (int s0 = 0; s0 < S_; s0 += 16) {
#pragma unroll
        for (int i = 0; i < 2; i++) {
            int slot = tid + i * 256;
            int r = slot >> 5;
            int c = (slot & 31) << 2;
            float4 kv = *(const float4*)(Kp + (size_t)(s0 + r) * D_ + c);
            kv.x = phi1(kv.x); kv.y = phi1(kv.y);
            kv.z = phi1(kv.z); kv.w = phi1(kv.w);
            *(float4*)&sK[r][c] = kv;
            *(float4*)&sV[r][c] = *(const float4*)(Vp + (size_t)(s0 + r) * D_ + c);
        }
        __syncthreads();

        if (tid < 128) {
#pragma unroll
            for (int r = 0; r < 16; r++) nacc += sK[r][tid];
        }

#pragma unroll
        for (int r = 0; r < 16; r++) {
            float a[8];
            *(float4*)&a[0] = *(float4*)&sK[r][k0];
            *(float4*)&a[4] = *(float4*)&sK[r][k0 + 4];
            ulonglong2 b01 = *(const ulonglong2*)&sV[r][v0];
            ulonglong2 b23 = *(const ulonglong2*)&sV[r][v0 + 4];
            unsigned long long Bp[4] = { b01.x, b01.y, b23.x, b23.y };
#pragma unroll
            for (int i = 0; i < 8; i++) {
                unsigned long long ad = fdup(a[i]);
#pragma unroll
                for (int j = 0; j < 4; j++) ffma2(acc[i][j], ad, Bp[j]);
            }
        }
        __syncthreads();
    }

    float* mp = g_mem + (size_t)bh * D_ * D_;
#pragma unroll
    for (int i = 0; i < 8; i++) {
        float o[8];
#pragma unroll
        for (int j = 0; j < 4; j++) {
            float2 v = f2unpack(acc[i][j]);
            o[2 * j] = v.x; o[2 * j + 1] = v.y;
        }
        *(float4*)(mp + (size_t)(k0 + i) * D_ + v0)     = *(float4*)&o[0];
        *(float4*)(mp + (size_t)(k0 + i) * D_ + v0 + 4) = *(float4*)&o[4];
    }
    if (tid < 128) g_nrm[bh * D_ + tid] = nacc;
}

// ---------------------------------------------------------------------------
// Kernel 2: retrieved = phiQ @ memory, denom = phiQ . norm,
//           attn = gw*retrieved/denom + lw*local, packed to [b,s,h*D+d]
// grid (S/64, BH); 256 threads; thread tile 4(s) x 8(v)
// ---------------------------------------------------------------------------
__global__ __launch_bounds__(256) void k_retrieve(const float* __restrict__ Qin,
                                                  const float* __restrict__ Lin,
                                                  const float* __restrict__ bal)
{
    __shared__ float sQ[64][128];
    __shared__ float sM[16][128];
    __shared__ float sN[128];

    const int bh = blockIdx.y;
    const int s0 = blockIdx.x * 64;
    const int h  = bh & (H_ - 1);
    const int b  = bh >> 5;
    const int tid = threadIdx.x;

    const float* Qp = Qin + (size_t)bh * S_ * D_ + (size_t)s0 * D_;
#pragma unroll
    for (int i = 0; i < 8; i++) {
        int slot = tid + i * 256;
        int r = slot >> 5;
        int c = (slot & 31) << 2;
        float4 q = *(const float4*)(Qp + (size_t)r * D_ + c);
        q.x = phi1(q.x); q.y = phi1(q.y);
        q.z = phi1(q.z); q.w = phi1(q.w);
        *(float4*)&sQ[r][c] = q;
    }
    if (tid < 128) sN[tid] = g_nrm[bh * D_ + tid];

    const int tx  = tid & 15, ty = tid >> 4;
    const int v0  = tx * 8,  sl0 = ty * 4;

    unsigned long long acc[4][4];
#pragma unroll
    for (int i = 0; i < 4; i++)
#pragma unroll
        for (int j = 0; j < 4; j++) acc[i][j] = 0ULL;
    float dacc[4] = {0.f, 0.f, 0.f, 0.f};

    const float* mp = g_mem + (size_t)bh * D_ * D_;

    for (int kc = 0; kc < D_; kc += 16) {
#pragma unroll
        for (int i = 0; i < 2; i++) {
            int slot = tid + i * 256;
            int r = slot >> 5;
            int c = (slot & 31) << 2;
            *(float4*)&sM[r][c] = *(const float4*)(mp + (size_t)(kc + r) * D_ + c);
        }
        __syncthreads();   // first iteration also covers sQ / sN

#pragma unroll
        for (int kk = 0; kk < 16; kk++) {
            ulonglong2 b01 = *(const ulonglong2*)&sM[kk][v0];
            ulonglong2 b23 = *(const ulonglong2*)&sM[kk][v0 + 4];
            unsigned long long Bp[4] = { b01.x, b01.y, b23.x, b23.y };
            float nk = sN[kc + kk];
#pragma unroll
            for (int i = 0; i < 4; i++) {
                float ai = sQ[sl0 + i][kc + kk];
                unsigned long long ad = fdup(ai);
#pragma unroll
                for (int j = 0; j < 4; j++) ffma2(acc[i][j], ad, Bp[j]);
                dacc[i] += ai * nk;
            }
        }
        __syncthreads();
    }

    float bf = bal[h];
    float gw = 1.f / (1.f + __expf(-bf));
    float lw = 1.f / (1.f + __expf(-(1.f - bf)));

    const float* lp = Lin + (size_t)bh * S_ * D_ + (size_t)s0 * D_;
    float* op = g_attn + (size_t)(b * S_ + s0) * DM_ + (size_t)h * D_;

#pragma unroll
    for (int i = 0; i < 4; i++) {
        float r[8];
#pragma unroll
        for (int j = 0; j < 4; j++) {
            float2 v = f2unpack(acc[i][j]);
            r[2 * j] = v.x; r[2 * j + 1] = v.y;
        }
        float rd = gw / dacc[i];  // fold gw into the division
        int sl = sl0 + i;
        float4 l0 = *(const float4*)(lp + (size_t)sl * D_ + v0);
        float4 l1 = *(const float4*)(lp + (size_t)sl * D_ + v0 + 4);
        float4 o0, o1;
        o0.x = r[0] * rd + lw * l0.x;
        o0.y = r[1] * rd + lw * l0.y;
        o0.z = r[2] * rd + lw * l0.z;
        o0.w = r[3] * rd + lw * l0.w;
        o1.x = r[4] * rd + lw * l1.x;
        o1.y = r[5] * rd + lw * l1.y;
        o1.z = r[6] * rd + lw * l1.z;
        o1.w = r[7] * rd + lw * l1.w;
        *(float4*)(op + (size_t)sl * DM_ + v0)     = o0;
        *(float4*)(op + (size_t)sl * DM_ + v0 + 4) = o1;
    }
}

// ---------------------------------------------------------------------------
// Kernel 3: out[m,n] = sum_k attn[m,k] * w_o[n,k]   (M=8192, N=4096, K=4096)
// 128x128 block tile, kc=16, 8x8 per thread, FFMA2 inner loop,
// software-pipelined global loads.
// ---------------------------------------------------------------------------
__global__ __launch_bounds__(256, 2) void k_proj(const float* __restrict__ Wo,
                                                 float* __restrict__ Out)
{
    __shared__ float sA[16][132];   // [k][m], padded, 528B rows (16B aligned)
    __shared__ float sB[16][132];   // [k][n]

    const int n0  = blockIdx.x * 128;
    const int m0  = blockIdx.y * 128;
    const int tid = threadIdx.x;
    const int tx  = tid & 15, ty = tid >> 4;

    unsigned long long acc[8][4];
#pragma unroll
    for (int i = 0; i < 8; i++)
#pragma unroll
        for (int j = 0; j < 4; j++) acc[i][j] = 0ULL;

    // prefetch registers for the software pipeline
    float4 pa[2], pw[2];
    int    pr[2], pk[2];

#pragma unroll
    for (int i = 0; i < 2; i++) {
        int slot = tid + i * 256;
        pr[i] = slot >> 2;
        pk[i] = (slot & 3) << 2;
        pa[i] = *(const float4*)(g_attn + (size_t)(m0 + pr[i]) * DM_ + pk[i]);
        pw[i] = *(const float4*)(Wo     + (size_t)(n0 + pr[i]) * DM_ + pk[i]);
    }

    for (int k0 = 0; k0 < DM_; k0 += 16) {
        // commit prefetched tile to smem (transpose to [k][m])
#pragma unroll
        for (int i = 0; i < 2; i++) {
            int r = pr[i], kq = pk[i];
            sA[kq + 0][r] = pa[i].x; sA[kq + 1][r] = pa[i].y;
            sA[kq + 2][r] = pa[i].z; sA[kq + 3][r] = pa[i].w;
            sB[kq + 0][r] = pw[i].x; sB[kq + 1][r] = pw[i].y;
            sB[kq + 2][r] = pw[i].z; sB[kq + 3][r] = pw[i].w;
        }
        __syncthreads();

        // prefetch next tile while computing this one
        if (k0 + 16 < DM_) {
#pragma unroll
            for (int i = 0; i < 2; i++) {
                pa[i] = *(const float4*)(g_attn + (size_t)(m0 + pr[i]) * DM_ + (k0 + 16) + pk[i]);
                pw[i] = *(const float4*)(Wo     + (size_t)(n0 + pr[i]) * DM_ + (k0 + 16) + pk[i]);
            }
        }

#pragma unroll
        for (int k = 0; k < 16; k++) {
            float a[8];
            *(float4*)&a[0] = *(float4*)&sA[k][ty * 8];
            *(float4*)&a[4] = *(float4*)&sA[k][ty * 8 + 4];
            ulonglong2 b01 = *(const ulonglong2*)&sB[k][tx * 8];
            ulonglong2 b23 = *(const ulonglong2*)&sB[k][tx * 8 + 4];
            unsigned long long Bp[4] = { b01.x, b01.y, b23.x, b23.y };
#pragma unroll
            for (int i = 0; i < 8; i++) {
                unsigned long long ad = fdup(a[i]);
#pragma unroll
                for (int j = 0; j < 4; j++) ffma2(acc[i][j], ad, Bp[j]);
            }
        }
        __syncthreads();
    }

#pragma unroll
    for (int i = 0; i < 8; i++) {
        float o[8];
#pragma unroll
        for (int j = 0; j < 4; j++) {
            float2 v = f2unpack(acc[i][j]);
            o[2 * j] = v.x; o[2 * j + 1] = v.y;
        }
        float* cp = Out + (size_t)(m0 + ty * 8 + i) * DM_ + n0 + tx * 8;
        *(float4*)cp       = *(float4*)&o[0];
        *(float4*)(cp + 4) = *(float4*)&o[4];
    }
}

// ---------------------------------------------------------------------------
// kernel_launch
// inputs: 0=query, 1=key, 2=value, 3=local_attn_outputs, 4=balance, 5=w_o
// ---------------------------------------------------------------------------
extern "C" void kernel_launch(void* const* d_in, const int* in_sizes, int n_in,
                              void* d_out, int out_size)
{
    const float* Q   = (const float*)d_in[0];
    const float* K   = (const float*)d_in[1];
    const float* V   = (const float*)d_in[2];
    const float* L   = (const float*)d_in[3];
    const float* bal = (const float*)d_in[4];
    const float* Wo  = (const float*)d_in[5];
    float* out = (float*)d_out;

    k_memory<<<BH_, 256>>>(K, V);

    dim3 g2(S_ / 64, BH_);
    k_retrieve<<<g2, 256>>>(Q, L, bal);

    dim3 g3(DM_ / 128, M_ / 128);
    k_proj<<<g3, 256>>>(Wo, out);
}